// round 7
// baseline (speedup 1.0000x reference)
#include <cuda_runtime.h>
#include <cuda_fp16.h>
#include <cstdint>
#include <cstddef>

// ---------------- problem constants ----------------
static constexpr int DK   = 4096;          // inner dim == output dim
static constexpr int MTOT = 4096;          // B*S
static constexpr int TM = 128, TN = 128, TK = 64;
static constexpr int NMT = MTOT / TM;      // 32
static constexpr int NNT = DK / TN;        // 32
static constexpr int NKS = DK / TK;        // 64 k-stages per tile
static constexpr int TOTAL_TILES = NMT * NNT;   // 1024
static constexpr int GRID = 296;           // 148 SMs x 2 CTAs (persistent)
static constexpr int STAGES = 3;
static constexpr int A_STAGE = TM * TK * 2;              // 16384
static constexpr int B_STAGE = TK * TN * 2;              // 16384
static constexpr int STAGE_BYTES = A_STAGE + B_STAGE;    // 32768
static constexpr int SMEM_BYTES  = 1024 + STAGES * STAGE_BYTES; // 99328 -> 2 CTAs/SM

// ---------------- scratch (pre-packed, pre-swizzled fp16 tiles) -------------
__device__ __align__(1024) __half g_A[(size_t)NMT * NKS * TM * TK]; // 32MB
__device__ __align__(1024) __half g_B[(size_t)NNT * NKS * TK * TN]; // 32MB
__device__ float g_px[(size_t)MTOT * NKS]; // per-(row, ktile) partial sums, 1MB
__device__ float g_rowsum[MTOT];

// ---------------- helpers ----------------
__device__ __forceinline__ uint32_t smem_u32(const void* p) {
    uint32_t a;
    asm("{ .reg .u64 t; cvta.to.shared.u64 t, %1; cvt.u32.u64 %0, t; }"
        : "=r"(a) : "l"(p));
    return a;
}
// A tiles: 128B rows -> XOR bits[6:4] with bits[9:7]
__device__ __forceinline__ uint32_t swzA(uint32_t off) {
    return off ^ ((off >> 3) & 0x70);
}
// B tiles: 256B rows -> XOR bits[6:4] with bits[10:8]
__device__ __forceinline__ uint32_t swzB(uint32_t off) {
    return off ^ ((off >> 4) & 0x70);
}

#define MBAR_INIT(mbar, cnt) \
    asm volatile("mbarrier.init.shared.b64 [%0], %1;" :: "r"(mbar), "r"(cnt) : "memory")
#define MBAR_ARRIVE(mbar) \
    asm volatile("mbarrier.arrive.shared.b64 _, [%0];" :: "r"(mbar) : "memory")
#define MBAR_EXPECT_TX(mbar, bytes) \
    asm volatile("mbarrier.arrive.expect_tx.shared.b64 _, [%0], %1;" \
                 :: "r"(mbar), "r"(bytes) : "memory")
#define MBAR_WAIT(mbar, parity) do {                                          \
    asm volatile(                                                             \
        "{\n\t.reg .pred P1;\n\t"                                             \
        "W_%=:\n\t"                                                           \
        "mbarrier.try_wait.parity.acquire.cta.shared::cta.b64 P1, [%0], %1, 0x989680;\n\t" \
        "@P1 bra.uni D_%=;\n\t"                                               \
        "bra.uni W_%=;\n\t"                                                   \
        "D_%=:\n\t}"                                                          \
        :: "r"((uint32_t)(mbar)), "r"((uint32_t)(parity)) : "memory");        \
} while (0)
#define BULK_G2S(dst, src, bytes, mbar)                                       \
    asm volatile(                                                             \
        "cp.async.bulk.shared::cluster.global.mbarrier::complete_tx::bytes "  \
        "[%0], [%1], %2, [%3];"                                               \
        :: "r"((uint32_t)(dst)), "l"(src), "r"((uint32_t)(bytes)),            \
           "r"((uint32_t)(mbar)) : "memory")

#define LDSM_X4(r0, r1, r2, r3, addr)                                         \
    asm volatile("ldmatrix.sync.aligned.m8n8.x4.shared.b16 {%0,%1,%2,%3}, [%4];" \
        : "=r"(r0), "=r"(r1), "=r"(r2), "=r"(r3) : "r"(addr))
#define LDSM_X4_T(r0, r1, r2, r3, addr)                                       \
    asm volatile("ldmatrix.sync.aligned.m8n8.x4.trans.shared.b16 {%0,%1,%2,%3}, [%4];" \
        : "=r"(r0), "=r"(r1), "=r"(r2), "=r"(r3) : "r"(addr))

#define MMA16816F16(d, a, b0, b1)                                             \
    asm volatile(                                                             \
        "mma.sync.aligned.m16n8k16.row.col.f32.f16.f16.f32 "                  \
        "{%0,%1,%2,%3}, {%4,%5,%6,%7}, {%8,%9}, {%0,%1,%2,%3};"               \
        : "+f"((d)[0]), "+f"((d)[1]), "+f"((d)[2]), "+f"((d)[3])              \
        : "r"((a)[0]), "r"((a)[1]), "r"((a)[2]), "r"((a)[3]),                 \
          "r"(b0), "r"(b1))

// ---------------- pack kernels ----------------
// A: x fp32 -> fp16 tiles [mt][ks][128 rows x 128B, swzA] + per-(row,ks) sums.
__global__ void __launch_bounds__(256) pack_x_kernel(const float* __restrict__ x) {
    int b = blockIdx.x;                 // mt*64 + ks
    int mt = b >> 6, ks = b & 63;
    size_t base = (size_t)b * A_STAGE;
#pragma unroll
    for (int p = 0; p < 4; p++) {
        int idx = threadIdx.x + p * 256;            // [0,1024)
        int ml = idx >> 3, k8 = idx & 7;
        size_t gm = (size_t)(mt * 128 + ml) * DK + ks * 64 + k8 * 8;
        float4 f0 = *reinterpret_cast<const float4*>(x + gm);
        float4 f1 = *reinterpret_cast<const float4*>(x + gm + 4);
        float v[8] = {f0.x, f0.y, f0.z, f0.w, f1.x, f1.y, f1.z, f1.w};
        uint32_t w[4];
        float s = 0.0f;
#pragma unroll
        for (int i = 0; i < 4; i++) {
            s += (v[2 * i] + v[2 * i + 1]);
            __half h0 = __float2half_rn(v[2 * i]);
            __half h1 = __float2half_rn(v[2 * i + 1]);
            w[i] = (uint32_t)__half_as_ushort(h0) |
                   ((uint32_t)__half_as_ushort(h1) << 16);
        }
        uint32_t off = swzA((uint32_t)(ml * 128 + k8 * 16));
        *reinterpret_cast<uint4*>((char*)g_A + base + off) =
            make_uint4(w[0], w[1], w[2], w[3]);
        // deterministic 8-lane tree sum (lanes of one row are aligned groups)
        s += __shfl_xor_sync(0xffffffffu, s, 1);
        s += __shfl_xor_sync(0xffffffffu, s, 2);
        s += __shfl_xor_sync(0xffffffffu, s, 4);
        if ((threadIdx.x & 7) == 0)
            g_px[(size_t)(mt * 128 + ml) * NKS + ks] = s;
    }
}

// reduce per-row partials (fixed serial order -> deterministic)
__global__ void __launch_bounds__(256) rowsum_reduce_kernel() {
    int r = blockIdx.x * 256 + threadIdx.x;
    const float* p = g_px + (size_t)r * NKS;
    float s = 0.0f;
#pragma unroll
    for (int i = 0; i < NKS; i++) s += p[i];
    g_rowsum[r] = s;
}

// B: q[k][n] int32 (0..255, exact in fp16) -> tiles [nt][ks][64 k x 256B, swzB]
__global__ void __launch_bounds__(256) pack_q_kernel(const int* __restrict__ q) {
    int b = blockIdx.x;                 // nt*64 + ks
    int nt = b >> 6, ks = b & 63;
    size_t base = (size_t)b * B_STAGE;
#pragma unroll
    for (int p = 0; p < 4; p++) {
        int idx = threadIdx.x + p * 256;            // [0,1024)
        int kl = idx >> 4, c8 = idx & 15;           // 64 rows x 16 chunks of 8n
        const int* src = q + (size_t)(ks * 64 + kl) * DK + nt * 128 + c8 * 8;
        int4 q0 = *reinterpret_cast<const int4*>(src);
        int4 q1 = *reinterpret_cast<const int4*>(src + 4);
        int vi[8] = {q0.x, q0.y, q0.z, q0.w, q1.x, q1.y, q1.z, q1.w};
        uint32_t w[4];
#pragma unroll
        for (int i = 0; i < 4; i++) {
            __half b0 = __float2half_rn((float)vi[2 * i]);
            __half b1 = __float2half_rn((float)vi[2 * i + 1]);
            w[i] = (uint32_t)__half_as_ushort(b0) |
                   ((uint32_t)__half_as_ushort(b1) << 16);
        }
        uint32_t off = swzB((uint32_t)(kl * 256 + c8 * 16));
        *reinterpret_cast<uint4*>((char*)g_B + base + off) =
            make_uint4(w[0], w[1], w[2], w[3]);
    }
}

// ---------------- main GEMM: persistent CTAs, seamless cross-tile pipeline --
__global__ void __launch_bounds__(256, 2)
ffq_gemm_kernel(const float* __restrict__ scale, const int* __restrict__ zp,
                const float* __restrict__ bias, float* __restrict__ out) {
    extern __shared__ char smem_raw[];
    uint32_t sb = (smem_u32(smem_raw) + 1023u) & ~1023u;   // ctrl base
    const uint32_t data = sb + 1024;                       // stage s at data + s*32768

    const int tid = threadIdx.x;
    const int wid = tid >> 5, lid = tid & 31;
    const int bid = blockIdx.x;
    const int mwarp = wid & 3;            // 4 M-rows of 32
    const int nwarp = wid >> 2;           // 2 N-cols of 64

    const int ntiles = (TOTAL_TILES - bid + GRID - 1) / GRID;   // 3 or 4
    const int total_gg = ntiles * NKS;

    // full[s] @ sb+8s (tx-based), empty[s] @ sb+64+8s (8 warp arrivals)
    if (tid == 0) {
#pragma unroll
        for (int s = 0; s < STAGES; s++) {
            MBAR_INIT(sb + 8 * s, 1);
            MBAR_INIT(sb + 64 + 8 * s, 8);
        }
        asm volatile("fence.proxy.async.shared::cta;" ::: "memory");
    }
    __syncthreads();

    // prologue: fill stages 0..2 with first tile's ks = 0..2
    if (tid == 0) {
        int nt0 = bid & 31, mt0 = bid >> 5;
#pragma unroll
        for (int s = 0; s < STAGES; s++) {
            const char* srcA = (const char*)g_A + (size_t)(mt0 * NKS + s) * A_STAGE;
            const char* srcB = (const char*)g_B + (size_t)(nt0 * NKS + s) * B_STAGE;
            uint32_t st = data + s * STAGE_BYTES;
            MBAR_EXPECT_TX(sb + 8 * s, STAGE_BYTES);
            BULK_G2S(st,           srcA, A_STAGE, sb + 8 * s);
            BULK_G2S(st + A_STAGE, srcB, B_STAGE, sb + 8 * s);
        }
    }

    // per-lane ldmatrix address components
    const int lg = lid >> 3, li = lid & 7;
    const uint32_t xorc  = (uint32_t)li << 4;
    const uint32_t a_row = (uint32_t)(mwarp * 32 + (lg & 1) * 8 + li);
    const uint32_t acolh = (uint32_t)((lg >> 1) * 16);
    const uint32_t b_klo = (uint32_t)((lg & 1) * 8 + li);
    const uint32_t bcolh = (uint32_t)(nwarp * 128 + (lg >> 1) * 16);
    const int t4 = lid >> 2;
    const int c2 = (lid & 3) * 2;

    int s = 0, ph = 0;

#pragma unroll 1
    for (int ti = 0; ti < ntiles; ++ti) {
        const int tile = bid + ti * GRID;
        const int nt = tile & 31, mtb = tile >> 5;

        float acc[2][8][4];
#pragma unroll
        for (int i = 0; i < 2; i++)
#pragma unroll
            for (int j = 0; j < 8; j++)
#pragma unroll
                for (int c = 0; c < 4; c++) acc[i][j][c] = 0.0f;

#pragma unroll 1
        for (int g = 0; g < NKS; ++g) {
            MBAR_WAIT(sb + 8 * s, ph);

            uint32_t sA = data + s * STAGE_BYTES;
            uint32_t sB = sA + A_STAGE;
#pragma unroll
            for (int k16 = 0; k16 < 4; ++k16) {
                uint32_t a0[4], a1[4];
                uint32_t ra = a_row * 128 + (((uint32_t)(k16 * 32) + acolh) ^ xorc);
                LDSM_X4(a0[0], a0[1], a0[2], a0[3], sA + ra);
                LDSM_X4(a1[0], a1[1], a1[2], a1[3], sA + ra + 16 * 128);
#pragma unroll
                for (int ng = 0; ng < 4; ++ng) {
                    uint32_t b0, b1, b2, b3;
                    uint32_t rb = sB + (b_klo + k16 * 16) * 256 +
                                  (((uint32_t)(ng * 32) + bcolh) ^ xorc);
                    LDSM_X4_T(b0, b1, b2, b3, rb);
                    MMA16816F16(acc[0][2 * ng],     a0, b0, b1);
                    MMA16816F16(acc[0][2 * ng + 1], a0, b2, b3);
                    MMA16816F16(acc[1][2 * ng],     a1, b0, b1);
                    MMA16816F16(acc[1][2 * ng + 1], a1, b2, b3);
                }
            }

            if (lid == 0) MBAR_ARRIVE(sb + 64 + 8 * s);

            // refill this stage with global iteration gg+3 (crosses tile edge)
            if (tid == 0) {
                int gg = ti * NKS + g + STAGES;
                if (gg < total_gg) {
                    int t2  = bid + (gg >> 6) * GRID;
                    int ks  = gg & (NKS - 1);
                    int nt2 = t2 & 31, mt2 = t2 >> 5;
                    const char* srcA = (const char*)g_A + (size_t)(mt2 * NKS + ks) * A_STAGE;
                    const char* srcB = (const char*)g_B + (size_t)(nt2 * NKS + ks) * B_STAGE;
                    MBAR_WAIT(sb + 64 + 8 * s, ph);   // all 8 warps done
                    MBAR_EXPECT_TX(sb + 8 * s, STAGE_BYTES);
                    BULK_G2S(sA, srcA, A_STAGE, sb + 8 * s);
                    BULK_G2S(sB, srcB, B_STAGE, sb + 8 * s);
                }
            }

            if (++s == STAGES) { s = 0; ph ^= 1; }
        }

        // ---- per-tile epilogue: out = acc*scale - rowsum*zp*scale + bias ----
#pragma unroll
        for (int mt = 0; mt < 2; ++mt) {
            int m0 = mtb * 128 + mwarp * 32 + mt * 16 + t4;
            float rs0 = g_rowsum[m0];
            float rs1 = g_rowsum[m0 + 8];
            float* row0 = out + (size_t)m0 * DK;
            float* row1 = row0 + (size_t)8 * DK;
#pragma unroll
            for (int nj = 0; nj < 8; ++nj) {
                int n = nt * 128 + nwarp * 64 + nj * 8 + c2;
                float sc0 = __ldg(scale + n),     sc1 = __ldg(scale + n + 1);
                float bi0 = __ldg(bias + n),      bi1 = __ldg(bias + n + 1);
                float zs0 = (float)__ldg(zp + n)     * sc0;
                float zs1 = (float)__ldg(zp + n + 1) * sc1;
                float2 o0, o1;
                o0.x = acc[mt][nj][0] * sc0 + bi0 - rs0 * zs0;
                o0.y = acc[mt][nj][1] * sc1 + bi1 - rs0 * zs1;
                o1.x = acc[mt][nj][2] * sc0 + bi0 - rs1 * zs0;
                o1.y = acc[mt][nj][3] * sc1 + bi1 - rs1 * zs1;
                *reinterpret_cast<float2*>(row0 + n) = o0;
                *reinterpret_cast<float2*>(row1 + n) = o1;
            }
        }
    }
}

// ---------------- launch ----------------
extern "C" void kernel_launch(void* const* d_in, const int* in_sizes, int n_in,
                              void* d_out, int out_size) {
    const float* x     = (const float*)d_in[0];
    const int*   q     = (const int*)  d_in[1];
    const float* scale = (const float*)d_in[2];
    const int*   zp    = (const int*)  d_in[3];
    const float* bias  = (const float*)d_in[4];
    float* out = (float*)d_out;

    cudaFuncSetAttribute(ffq_gemm_kernel,
                         cudaFuncAttributeMaxDynamicSharedMemorySize, SMEM_BYTES);

    pack_x_kernel<<<NMT * NKS, 256>>>(x);        // 2048 blocks (+ row partials)
    pack_q_kernel<<<NNT * NKS, 256>>>(q);        // 2048 blocks
    rowsum_reduce_kernel<<<MTOT / 256, 256>>>(); // 16 blocks
    ffq_gemm_kernel<<<GRID, 256, SMEM_BYTES>>>(scale, zp, bias, out);
}

// round 8
// speedup vs baseline: 1.0459x; 1.0459x over previous
#include <cuda_runtime.h>
#include <cuda_fp16.h>
#include <cstdint>
#include <cstddef>

// ---------------- problem constants ----------------
static constexpr int DK   = 4096;          // inner dim == output dim
static constexpr int MTOT = 4096;          // B*S
static constexpr int TM = 128, TN = 128, TK = 64;
static constexpr int NMT = MTOT / TM;      // 32
static constexpr int NNT = DK / TN;        // 32
static constexpr int NKS = DK / TK;        // 64 k-stages, single pass
static constexpr int STAGES = 3;
static constexpr int A_STAGE = TM * TK * 2;              // 16384
static constexpr int B_STAGE = TK * TN * 2;              // 16384
static constexpr int STAGE_BYTES = A_STAGE + B_STAGE;    // 32768
static constexpr int SMEM_BYTES  = 1024 + STAGES * STAGE_BYTES; // 99328 -> 2 CTAs/SM

// ---------------- scratch (pre-packed, pre-swizzled fp16 tiles) -------------
__device__ __align__(1024) __half g_A[(size_t)NMT * NKS * TM * TK]; // 32MB
__device__ __align__(1024) __half g_B[(size_t)NNT * NKS * TK * TN]; // 32MB
__device__ float g_px[(size_t)MTOT * NKS]; // per-(row, ktile) partial sums, 1MB
__device__ float g_rowsum[MTOT];

// ---------------- helpers ----------------
__device__ __forceinline__ uint32_t smem_u32(const void* p) {
    uint32_t a;
    asm("{ .reg .u64 t; cvta.to.shared.u64 t, %1; cvt.u32.u64 %0, t; }"
        : "=r"(a) : "l"(p));
    return a;
}
// A tiles: 128B rows -> XOR bits[6:4] with bits[9:7]
__device__ __forceinline__ uint32_t swzA(uint32_t off) {
    return off ^ ((off >> 3) & 0x70);
}
// B tiles: 256B rows -> XOR bits[6:4] with bits[10:8]
__device__ __forceinline__ uint32_t swzB(uint32_t off) {
    return off ^ ((off >> 4) & 0x70);
}

#define MBAR_INIT(mbar, cnt) \
    asm volatile("mbarrier.init.shared.b64 [%0], %1;" :: "r"(mbar), "r"(cnt) : "memory")
#define MBAR_ARRIVE(mbar) \
    asm volatile("mbarrier.arrive.shared.b64 _, [%0];" :: "r"(mbar) : "memory")
#define MBAR_EXPECT_TX(mbar, bytes) \
    asm volatile("mbarrier.arrive.expect_tx.shared.b64 _, [%0], %1;" \
                 :: "r"(mbar), "r"(bytes) : "memory")
#define MBAR_WAIT(mbar, parity) do {                                          \
    asm volatile(                                                             \
        "{\n\t.reg .pred P1;\n\t"                                             \
        "W_%=:\n\t"                                                           \
        "mbarrier.try_wait.parity.acquire.cta.shared::cta.b64 P1, [%0], %1, 0x989680;\n\t" \
        "@P1 bra.uni D_%=;\n\t"                                               \
        "bra.uni W_%=;\n\t"                                                   \
        "D_%=:\n\t}"                                                          \
        :: "r"((uint32_t)(mbar)), "r"((uint32_t)(parity)) : "memory");        \
} while (0)
#define BULK_G2S(dst, src, bytes, mbar)                                       \
    asm volatile(                                                             \
        "cp.async.bulk.shared::cluster.global.mbarrier::complete_tx::bytes "  \
        "[%0], [%1], %2, [%3];"                                               \
        :: "r"((uint32_t)(dst)), "l"(src), "r"((uint32_t)(bytes)),            \
           "r"((uint32_t)(mbar)) : "memory")

#define LDSM_X4(r0, r1, r2, r3, addr)                                         \
    asm volatile("ldmatrix.sync.aligned.m8n8.x4.shared.b16 {%0,%1,%2,%3}, [%4];" \
        : "=r"(r0), "=r"(r1), "=r"(r2), "=r"(r3) : "r"(addr))
#define LDSM_X4_T(r0, r1, r2, r3, addr)                                       \
    asm volatile("ldmatrix.sync.aligned.m8n8.x4.trans.shared.b16 {%0,%1,%2,%3}, [%4];" \
        : "=r"(r0), "=r"(r1), "=r"(r2), "=r"(r3) : "r"(addr))

#define MMA16816F16(d, a, b0, b1)                                             \
    asm volatile(                                                             \
        "mma.sync.aligned.m16n8k16.row.col.f32.f16.f16.f32 "                  \
        "{%0,%1,%2,%3}, {%4,%5,%6,%7}, {%8,%9}, {%0,%1,%2,%3};"               \
        : "+f"((d)[0]), "+f"((d)[1]), "+f"((d)[2]), "+f"((d)[3])              \
        : "r"((a)[0]), "r"((a)[1]), "r"((a)[2]), "r"((a)[3]),                 \
          "r"(b0), "r"(b1))

// ---------------- merged pack kernel ----------------
// blocks [0, 2048):      A pack  (mt*64 + ks)  + per-(row,ks) partial sums
// blocks [2048, 4096):   B pack  (nt*64 + ks)
__global__ void __launch_bounds__(256) pack_all_kernel(const float* __restrict__ x,
                                                       const int* __restrict__ q) {
    int b = blockIdx.x;
    if (b < NMT * NKS) {
        int mt = b >> 6, ks = b & 63;
        size_t base = (size_t)b * A_STAGE;
#pragma unroll
        for (int p = 0; p < 4; p++) {
            int idx = threadIdx.x + p * 256;            // [0,1024)
            int ml = idx >> 3, k8 = idx & 7;
            size_t gm = (size_t)(mt * 128 + ml) * DK + ks * 64 + k8 * 8;
            float4 f0 = *reinterpret_cast<const float4*>(x + gm);
            float4 f1 = *reinterpret_cast<const float4*>(x + gm + 4);
            float v[8] = {f0.x, f0.y, f0.z, f0.w, f1.x, f1.y, f1.z, f1.w};
            uint32_t w[4];
            float s = 0.0f;
#pragma unroll
            for (int i = 0; i < 4; i++) {
                s += (v[2 * i] + v[2 * i + 1]);
                __half h0 = __float2half_rn(v[2 * i]);
                __half h1 = __float2half_rn(v[2 * i + 1]);
                w[i] = (uint32_t)__half_as_ushort(h0) |
                       ((uint32_t)__half_as_ushort(h1) << 16);
            }
            uint32_t off = swzA((uint32_t)(ml * 128 + k8 * 16));
            *reinterpret_cast<uint4*>((char*)g_A + base + off) =
                make_uint4(w[0], w[1], w[2], w[3]);
            // deterministic 8-lane tree sum (one row = aligned 8-lane group)
            s += __shfl_xor_sync(0xffffffffu, s, 1);
            s += __shfl_xor_sync(0xffffffffu, s, 2);
            s += __shfl_xor_sync(0xffffffffu, s, 4);
            if ((threadIdx.x & 7) == 0)
                g_px[(size_t)(mt * 128 + ml) * NKS + ks] = s;
        }
    } else {
        b -= NMT * NKS;
        int nt = b >> 6, ks = b & 63;
        size_t base = (size_t)b * B_STAGE;
#pragma unroll
        for (int p = 0; p < 4; p++) {
            int idx = threadIdx.x + p * 256;            // [0,1024)
            int kl = idx >> 4, c8 = idx & 15;           // 64 rows x 16 chunks
            const int* src = q + (size_t)(ks * 64 + kl) * DK + nt * 128 + c8 * 8;
            int4 q0 = *reinterpret_cast<const int4*>(src);
            int4 q1 = *reinterpret_cast<const int4*>(src + 4);
            int vi[8] = {q0.x, q0.y, q0.z, q0.w, q1.x, q1.y, q1.z, q1.w};
            uint32_t w[4];
#pragma unroll
            for (int i = 0; i < 4; i++) {
                __half b0 = __float2half_rn((float)vi[2 * i]);
                __half b1 = __float2half_rn((float)vi[2 * i + 1]);
                w[i] = (uint32_t)__half_as_ushort(b0) |
                       ((uint32_t)__half_as_ushort(b1) << 16);
            }
            uint32_t off = swzB((uint32_t)(kl * 256 + c8 * 16));
            *reinterpret_cast<uint4*>((char*)g_B + base + off) =
                make_uint4(w[0], w[1], w[2], w[3]);
        }
    }
}

// reduce per-row partials (fixed serial order -> deterministic)
__global__ void __launch_bounds__(256) rowsum_reduce_kernel() {
    int r = blockIdx.x * 256 + threadIdx.x;
    const float* p = g_px + (size_t)r * NKS;
    float s = 0.0f;
#pragma unroll
    for (int i = 0; i < NKS; i++) s += p[i];
    g_rowsum[r] = s;
}

// ---------------- main GEMM: software-pipelined fragments, 3-stage, 2 CTA/SM
__global__ void __launch_bounds__(256, 2)
ffq_gemm_kernel(const float* __restrict__ scale, const int* __restrict__ zp,
                const float* __restrict__ bias, float* __restrict__ out) {
    extern __shared__ char smem_raw[];
    uint32_t sb = (smem_u32(smem_raw) + 1023u) & ~1023u;   // ctrl base
    const uint32_t data = sb + 1024;                       // stage s at data + s*32768

    const int tid = threadIdx.x;
    const int wid = tid >> 5, lid = tid & 31;
    const int nt = blockIdx.x, mtb = blockIdx.y;
    const int mwarp = wid & 3;            // 4 M-rows of 32
    const int nwarp = wid >> 2;           // 2 N-cols of 64

    // full[s] @ sb+8s (tx-based), empty[s] @ sb+64+8s (8 warp arrivals)
    if (tid == 0) {
#pragma unroll
        for (int s = 0; s < STAGES; s++) {
            MBAR_INIT(sb + 8 * s, 1);
            MBAR_INIT(sb + 64 + 8 * s, 8);
        }
        asm volatile("fence.proxy.async.shared::cta;" ::: "memory");
    }
    __syncthreads();

    // prologue: fill stages 0..2 with ks = s
    if (tid == 0) {
#pragma unroll
        for (int s = 0; s < STAGES; s++) {
            const char* srcA = (const char*)g_A + (size_t)(mtb * NKS + s) * A_STAGE;
            const char* srcB = (const char*)g_B + (size_t)(nt  * NKS + s) * B_STAGE;
            uint32_t st = data + s * STAGE_BYTES;
            MBAR_EXPECT_TX(sb + 8 * s, STAGE_BYTES);
            BULK_G2S(st,           srcA, A_STAGE, sb + 8 * s);
            BULK_G2S(st + A_STAGE, srcB, B_STAGE, sb + 8 * s);
        }
    }

    // per-lane ldmatrix address components
    const int lg = lid >> 3, li = lid & 7;
    const uint32_t xorc  = (uint32_t)li << 4;
    const uint32_t a_row = (uint32_t)(mwarp * 32 + (lg & 1) * 8 + li);
    const uint32_t acolh = (uint32_t)((lg >> 1) * 16);
    const uint32_t b_klo = (uint32_t)((lg & 1) * 8 + li);
    const uint32_t bcolh = (uint32_t)(nwarp * 128 + (lg >> 1) * 16);

    float acc[2][8][4];
#pragma unroll
    for (int i = 0; i < 2; i++)
#pragma unroll
        for (int j = 0; j < 8; j++)
#pragma unroll
            for (int c = 0; c < 4; c++) acc[i][j][c] = 0.0f;

    int s = 0, ph = 0;
#pragma unroll 1
    for (int g = 0; g < NKS; ++g) {
        MBAR_WAIT(sb + 8 * s, ph);

        uint32_t sA = data + s * STAGE_BYTES;
        uint32_t sB = sA + A_STAGE;

        // ---- software-pipelined fragment loop over 16 (k16, ng) pairs ----
        uint32_t a_cur[2][4], a_nxt[2][4], b_cur[4], b_nxt[4];
        {   // prime: A(k16=0), B(k16=0, ng=0)
            uint32_t ra = a_row * 128 + (acolh ^ xorc);
            LDSM_X4(a_cur[0][0], a_cur[0][1], a_cur[0][2], a_cur[0][3], sA + ra);
            LDSM_X4(a_cur[1][0], a_cur[1][1], a_cur[1][2], a_cur[1][3],
                    sA + ra + 16 * 128);
            uint32_t rb = sB + b_klo * 256 + (bcolh ^ xorc);
            LDSM_X4_T(b_cur[0], b_cur[1], b_cur[2], b_cur[3], rb);
        }
#pragma unroll
        for (int p = 0; p < 16; ++p) {
            const int k16 = p >> 2, ng = p & 3;
            if (p < 15) {
                const int pn = p + 1;
                const int k16n = pn >> 2, ngn = pn & 3;
                if (ngn == 0) {   // crossing into next k16: prefetch A too
                    uint32_t ra = a_row * 128 +
                                  (((uint32_t)(k16n * 32) + acolh) ^ xorc);
                    LDSM_X4(a_nxt[0][0], a_nxt[0][1], a_nxt[0][2], a_nxt[0][3],
                            sA + ra);
                    LDSM_X4(a_nxt[1][0], a_nxt[1][1], a_nxt[1][2], a_nxt[1][3],
                            sA + ra + 16 * 128);
                }
                uint32_t rb = sB + (b_klo + k16n * 16) * 256 +
                              (((uint32_t)(ngn * 32) + bcolh) ^ xorc);
                LDSM_X4_T(b_nxt[0], b_nxt[1], b_nxt[2], b_nxt[3], rb);
            }

            MMA16816F16(acc[0][2 * ng],     a_cur[0], b_cur[0], b_cur[1]);
            MMA16816F16(acc[0][2 * ng + 1], a_cur[0], b_cur[2], b_cur[3]);
            MMA16816F16(acc[1][2 * ng],     a_cur[1], b_cur[0], b_cur[1]);
            MMA16816F16(acc[1][2 * ng + 1], a_cur[1], b_cur[2], b_cur[3]);

            if (p < 15) {
#pragma unroll
                for (int i = 0; i < 4; i++) b_cur[i] = b_nxt[i];
                if (ng == 3) {
#pragma unroll
                    for (int mt = 0; mt < 2; mt++)
#pragma unroll
                        for (int i = 0; i < 4; i++) a_cur[mt][i] = a_nxt[mt][i];
                }
            }
        }

        if (lid == 0) MBAR_ARRIVE(sb + 64 + 8 * s);

        if (tid == 0 && g + STAGES < NKS) {
            MBAR_WAIT(sb + 64 + 8 * s, ph);      // all 8 warps done with stage
            int ks = g + STAGES;
            const char* srcA = (const char*)g_A + (size_t)(mtb * NKS + ks) * A_STAGE;
            const char* srcB = (const char*)g_B + (size_t)(nt  * NKS + ks) * B_STAGE;
            MBAR_EXPECT_TX(sb + 8 * s, STAGE_BYTES);
            BULK_G2S(sA, srcA, A_STAGE, sb + 8 * s);
            BULK_G2S(sB, srcB, B_STAGE, sb + 8 * s);
        }

        if (++s == STAGES) { s = 0; ph ^= 1; }
    }

    // ---- epilogue: out = acc*scale - rowsum*zp*scale + bias ----
    const int t4 = lid >> 2;
    const int c2 = (lid & 3) * 2;
#pragma unroll
    for (int mt = 0; mt < 2; ++mt) {
        int m0 = mtb * 128 + mwarp * 32 + mt * 16 + t4;
        float rs0 = g_rowsum[m0];
        float rs1 = g_rowsum[m0 + 8];
        float* row0 = out + (size_t)m0 * DK;
        float* row1 = row0 + (size_t)8 * DK;
#pragma unroll
        for (int nj = 0; nj < 8; ++nj) {
            int n = nt * 128 + nwarp * 64 + nj * 8 + c2;
            float sc0 = __ldg(scale + n),     sc1 = __ldg(scale + n + 1);
            float bi0 = __ldg(bias + n),      bi1 = __ldg(bias + n + 1);
            float zs0 = (float)__ldg(zp + n)     * sc0;
            float zs1 = (float)__ldg(zp + n + 1) * sc1;
            float2 o0, o1;
            o0.x = acc[mt][nj][0] * sc0 + bi0 - rs0 * zs0;
            o0.y = acc[mt][nj][1] * sc1 + bi1 - rs0 * zs1;
            o1.x = acc[mt][nj][2] * sc0 + bi0 - rs1 * zs0;
            o1.y = acc[mt][nj][3] * sc1 + bi1 - rs1 * zs1;
            *reinterpret_cast<float2*>(row0 + n) = o0;
            *reinterpret_cast<float2*>(row1 + n) = o1;
        }
    }
}

// ---------------- launch ----------------
extern "C" void kernel_launch(void* const* d_in, const int* in_sizes, int n_in,
                              void* d_out, int out_size) {
    const float* x     = (const float*)d_in[0];
    const int*   q     = (const int*)  d_in[1];
    const float* scale = (const float*)d_in[2];
    const int*   zp    = (const int*)  d_in[3];
    const float* bias  = (const float*)d_in[4];
    float* out = (float*)d_out;

    cudaFuncSetAttribute(ffq_gemm_kernel,
                         cudaFuncAttributeMaxDynamicSharedMemorySize, SMEM_BYTES);

    pack_all_kernel<<<2 * NMT * NKS, 256>>>(x, q);   // 4096 blocks (A+B packs)
    rowsum_reduce_kernel<<<MTOT / 256, 256>>>();     // 16 blocks
    ffq_gemm_kernel<<<dim3(NNT, NMT), 256, SMEM_BYTES>>>(scale, zp, bias, out);
}

// round 9
// speedup vs baseline: 1.0537x; 1.0075x over previous
#include <cuda_runtime.h>
#include <cuda_fp16.h>
#include <cstdint>
#include <cstddef>

// ---------------- problem constants ----------------
static constexpr int DK   = 4096;          // inner dim == output dim
static constexpr int MTOT = 4096;          // B*S
static constexpr int TM = 128, TN = 128, TK = 64;
static constexpr int NMT = MTOT / TM;      // 32
static constexpr int NNT = DK / TN;        // 32
static constexpr int NKS = DK / TK;        // 64 k-stages, single pass
static constexpr int STAGES = 3;
static constexpr int A_STAGE = TM * TK * 2;              // 16384
static constexpr int B_STAGE = TK * TN * 2;              // 16384
static constexpr int STAGE_BYTES = A_STAGE + B_STAGE;    // 32768
static constexpr int SMEM_BYTES  = 1024 + STAGES * STAGE_BYTES; // 99328 -> 2 CTAs/SM

// ---------------- scratch (pre-packed, pre-swizzled fp16 tiles) -------------
__device__ __align__(1024) __half g_A[(size_t)NMT * NKS * TM * TK]; // 32MB
__device__ __align__(1024) __half g_B[(size_t)NNT * NKS * TK * TN]; // 32MB
__device__ float g_px[(size_t)MTOT * NKS]; // per-(row, ktile) partial sums, 1MB
__device__ float g_rowsum[MTOT];

// ---------------- helpers ----------------
__device__ __forceinline__ uint32_t smem_u32(const void* p) {
    uint32_t a;
    asm("{ .reg .u64 t; cvta.to.shared.u64 t, %1; cvt.u32.u64 %0, t; }"
        : "=r"(a) : "l"(p));
    return a;
}
// A tiles: 128B rows -> XOR bits[6:4] with bits[9:7]
__device__ __forceinline__ uint32_t swzA(uint32_t off) {
    return off ^ ((off >> 3) & 0x70);
}
// B tiles: 256B rows -> XOR bits[6:4] with bits[10:8]
__device__ __forceinline__ uint32_t swzB(uint32_t off) {
    return off ^ ((off >> 4) & 0x70);
}

#define MBAR_INIT(mbar, cnt) \
    asm volatile("mbarrier.init.shared.b64 [%0], %1;" :: "r"(mbar), "r"(cnt) : "memory")
#define MBAR_ARRIVE(mbar) \
    asm volatile("mbarrier.arrive.shared.b64 _, [%0];" :: "r"(mbar) : "memory")
#define MBAR_EXPECT_TX(mbar, bytes) \
    asm volatile("mbarrier.arrive.expect_tx.shared.b64 _, [%0], %1;" \
                 :: "r"(mbar), "r"(bytes) : "memory")
#define MBAR_WAIT(mbar, parity) do {                                          \
    asm volatile(                                                             \
        "{\n\t.reg .pred P1;\n\t"                                             \
        "W_%=:\n\t"                                                           \
        "mbarrier.try_wait.parity.acquire.cta.shared::cta.b64 P1, [%0], %1, 0x989680;\n\t" \
        "@P1 bra.uni D_%=;\n\t"                                               \
        "bra.uni W_%=;\n\t"                                                   \
        "D_%=:\n\t}"                                                          \
        :: "r"((uint32_t)(mbar)), "r"((uint32_t)(parity)) : "memory");        \
} while (0)
#define BULK_G2S(dst, src, bytes, mbar)                                       \
    asm volatile(                                                             \
        "cp.async.bulk.shared::cluster.global.mbarrier::complete_tx::bytes "  \
        "[%0], [%1], %2, [%3];"                                               \
        :: "r"((uint32_t)(dst)), "l"(src), "r"((uint32_t)(bytes)),            \
           "r"((uint32_t)(mbar)) : "memory")

#define LDSM_X4(r0, r1, r2, r3, addr)                                         \
    asm volatile("ldmatrix.sync.aligned.m8n8.x4.shared.b16 {%0,%1,%2,%3}, [%4];" \
        : "=r"(r0), "=r"(r1), "=r"(r2), "=r"(r3) : "r"(addr))
#define LDSM_X4_T(r0, r1, r2, r3, addr)                                       \
    asm volatile("ldmatrix.sync.aligned.m8n8.x4.trans.shared.b16 {%0,%1,%2,%3}, [%4];" \
        : "=r"(r0), "=r"(r1), "=r"(r2), "=r"(r3) : "r"(addr))

#define MMA16816F16(d, a, b0, b1)                                             \
    asm volatile(                                                             \
        "mma.sync.aligned.m16n8k16.row.col.f32.f16.f16.f32 "                  \
        "{%0,%1,%2,%3}, {%4,%5,%6,%7}, {%8,%9}, {%0,%1,%2,%3};"               \
        : "+f"((d)[0]), "+f"((d)[1]), "+f"((d)[2]), "+f"((d)[3])              \
        : "r"((a)[0]), "r"((a)[1]), "r"((a)[2]), "r"((a)[3]),                 \
          "r"(b0), "r"(b1))

// ---------------- merged pack kernel ----------------
// blocks [0, 2048):      A pack  (mt*64 + ks)  + per-(row,ks) partial sums
// blocks [2048, 4096):   B pack  (nt*64 + ks)
__global__ void __launch_bounds__(256) pack_all_kernel(const float* __restrict__ x,
                                                       const int* __restrict__ q) {
    int b = blockIdx.x;
    if (b < NMT * NKS) {
        int mt = b >> 6, ks = b & 63;
        size_t base = (size_t)b * A_STAGE;
#pragma unroll
        for (int p = 0; p < 4; p++) {
            int idx = threadIdx.x + p * 256;            // [0,1024)
            int ml = idx >> 3, k8 = idx & 7;
            size_t gm = (size_t)(mt * 128 + ml) * DK + ks * 64 + k8 * 8;
            float4 f0 = *reinterpret_cast<const float4*>(x + gm);
            float4 f1 = *reinterpret_cast<const float4*>(x + gm + 4);
            float v[8] = {f0.x, f0.y, f0.z, f0.w, f1.x, f1.y, f1.z, f1.w};
            uint32_t w[4];
            float s = 0.0f;
#pragma unroll
            for (int i = 0; i < 4; i++) {
                s += (v[2 * i] + v[2 * i + 1]);
                __half h0 = __float2half_rn(v[2 * i]);
                __half h1 = __float2half_rn(v[2 * i + 1]);
                w[i] = (uint32_t)__half_as_ushort(h0) |
                       ((uint32_t)__half_as_ushort(h1) << 16);
            }
            uint32_t off = swzA((uint32_t)(ml * 128 + k8 * 16));
            *reinterpret_cast<uint4*>((char*)g_A + base + off) =
                make_uint4(w[0], w[1], w[2], w[3]);
            // deterministic 8-lane tree sum (one row = aligned 8-lane group)
            s += __shfl_xor_sync(0xffffffffu, s, 1);
            s += __shfl_xor_sync(0xffffffffu, s, 2);
            s += __shfl_xor_sync(0xffffffffu, s, 4);
            if ((threadIdx.x & 7) == 0)
                g_px[(size_t)(mt * 128 + ml) * NKS + ks] = s;
        }
    } else {
        b -= NMT * NKS;
        int nt = b >> 6, ks = b & 63;
        size_t base = (size_t)b * B_STAGE;
#pragma unroll
        for (int p = 0; p < 4; p++) {
            int idx = threadIdx.x + p * 256;            // [0,1024)
            int kl = idx >> 4, c8 = idx & 15;           // 64 rows x 16 chunks
            const int* src = q + (size_t)(ks * 64 + kl) * DK + nt * 128 + c8 * 8;
            int4 q0 = *reinterpret_cast<const int4*>(src);
            int4 q1 = *reinterpret_cast<const int4*>(src + 4);
            int vi[8] = {q0.x, q0.y, q0.z, q0.w, q1.x, q1.y, q1.z, q1.w};
            uint32_t w[4];
#pragma unroll
            for (int i = 0; i < 4; i++) {
                __half b0 = __float2half_rn((float)vi[2 * i]);
                __half b1 = __float2half_rn((float)vi[2 * i + 1]);
                w[i] = (uint32_t)__half_as_ushort(b0) |
                       ((uint32_t)__half_as_ushort(b1) << 16);
            }
            uint32_t off = swzB((uint32_t)(kl * 256 + c8 * 16));
            *reinterpret_cast<uint4*>((char*)g_B + base + off) =
                make_uint4(w[0], w[1], w[2], w[3]);
        }
    }
}

// reduce per-row partials (fixed serial order -> deterministic)
__global__ void __launch_bounds__(256) rowsum_reduce_kernel() {
    int r = blockIdx.x * 256 + threadIdx.x;
    const float* p = g_px + (size_t)r * NKS;
    float s = 0.0f;
#pragma unroll
    for (int i = 0; i < NKS; i++) s += p[i];
    g_rowsum[r] = s;
}

// ---------------- main GEMM: 4 warps, 64x64 warp tile (4:1 MMA:LDSM) --------
__global__ void __launch_bounds__(128, 2)
ffq_gemm_kernel(const float* __restrict__ scale, const int* __restrict__ zp,
                const float* __restrict__ bias, float* __restrict__ out) {
    extern __shared__ char smem_raw[];
    uint32_t sb = (smem_u32(smem_raw) + 1023u) & ~1023u;   // ctrl base
    const uint32_t data = sb + 1024;                       // stage s at data + s*32768

    const int tid = threadIdx.x;
    const int wid = tid >> 5, lid = tid & 31;
    const int nt = blockIdx.x, mtb = blockIdx.y;
    const int mwarp = wid & 1;            // 2 M-halves of 64
    const int nwarp = wid >> 1;           // 2 N-halves of 64

    // full[s] @ sb+8s (tx-based), empty[s] @ sb+64+8s (4 warp arrivals)
    if (tid == 0) {
#pragma unroll
        for (int s = 0; s < STAGES; s++) {
            MBAR_INIT(sb + 8 * s, 1);
            MBAR_INIT(sb + 64 + 8 * s, 4);
        }
        asm volatile("fence.proxy.async.shared::cta;" ::: "memory");
    }
    __syncthreads();

    // prologue: fill stages 0..2 with ks = s
    if (tid == 0) {
#pragma unroll
        for (int s = 0; s < STAGES; s++) {
            const char* srcA = (const char*)g_A + (size_t)(mtb * NKS + s) * A_STAGE;
            const char* srcB = (const char*)g_B + (size_t)(nt  * NKS + s) * B_STAGE;
            uint32_t st = data + s * STAGE_BYTES;
            MBAR_EXPECT_TX(sb + 8 * s, STAGE_BYTES);
            BULK_G2S(st,           srcA, A_STAGE, sb + 8 * s);
            BULK_G2S(st + A_STAGE, srcB, B_STAGE, sb + 8 * s);
        }
    }

    // per-lane ldmatrix address components
    const int lg = lid >> 3, li = lid & 7;
    const uint32_t xorc  = (uint32_t)li << 4;
    const uint32_t a_row = (uint32_t)(mwarp * 64 + (lg & 1) * 8 + li);   // + mt*16
    const uint32_t acolh = (uint32_t)((lg >> 1) * 16);                   // + k16*32
    const uint32_t b_klo = (uint32_t)((lg & 1) * 8 + li);                // + k16*16
    const uint32_t bcolh = (uint32_t)(nwarp * 128 + (lg >> 1) * 16);     // + ng*32

    float acc[4][8][4];
#pragma unroll
    for (int i = 0; i < 4; i++)
#pragma unroll
        for (int j = 0; j < 8; j++)
#pragma unroll
            for (int c = 0; c < 4; c++) acc[i][j][c] = 0.0f;

    int s = 0, ph = 0;
#pragma unroll 1
    for (int g = 0; g < NKS; ++g) {
        MBAR_WAIT(sb + 8 * s, ph);

        uint32_t sA = data + s * STAGE_BYTES;
        uint32_t sB = sA + A_STAGE;

        // fragment double-buffer across the 4 k16 groups
        uint32_t a_cur[4][4], a_nxt[4][4], b_cur[4][4], b_nxt[4][4];
        {   // prime k16 = 0: 4 A frags (m64) + 4 B frags (n64)
            uint32_t ra = a_row * 128 + (acolh ^ xorc);
#pragma unroll
            for (int mt = 0; mt < 4; ++mt)
                LDSM_X4(a_cur[mt][0], a_cur[mt][1], a_cur[mt][2], a_cur[mt][3],
                        sA + ra + mt * (16 * 128));
            uint32_t rbbase = sB + b_klo * 256;
#pragma unroll
            for (int ng = 0; ng < 4; ++ng)
                LDSM_X4_T(b_cur[ng][0], b_cur[ng][1], b_cur[ng][2], b_cur[ng][3],
                          rbbase + (((uint32_t)(ng * 32) + bcolh) ^ xorc));
        }

#pragma unroll
        for (int k16 = 0; k16 < 4; ++k16) {
            if (k16 < 3) {   // prefetch next k16 group (8 LDSM)
                uint32_t ra = a_row * 128 +
                              (((uint32_t)((k16 + 1) * 32) + acolh) ^ xorc);
#pragma unroll
                for (int mt = 0; mt < 4; ++mt)
                    LDSM_X4(a_nxt[mt][0], a_nxt[mt][1], a_nxt[mt][2], a_nxt[mt][3],
                            sA + ra + mt * (16 * 128));
                uint32_t rbbase = sB + (b_klo + (k16 + 1) * 16) * 256;
#pragma unroll
                for (int ng = 0; ng < 4; ++ng)
                    LDSM_X4_T(b_nxt[ng][0], b_nxt[ng][1], b_nxt[ng][2], b_nxt[ng][3],
                              rbbase + (((uint32_t)(ng * 32) + bcolh) ^ xorc));
            }

            // 32 HMMAs on current fragments
#pragma unroll
            for (int mt = 0; mt < 4; ++mt)
#pragma unroll
                for (int ng = 0; ng < 4; ++ng) {
                    MMA16816F16(acc[mt][2 * ng],     a_cur[mt],
                                b_cur[ng][0], b_cur[ng][1]);
                    MMA16816F16(acc[mt][2 * ng + 1], a_cur[mt],
                                b_cur[ng][2], b_cur[ng][3]);
                }

            if (k16 < 3) {
#pragma unroll
                for (int mt = 0; mt < 4; ++mt)
#pragma unroll
                    for (int i = 0; i < 4; ++i) {
                        a_cur[mt][i] = a_nxt[mt][i];
                        b_cur[mt][i] = b_nxt[mt][i];
                    }
            }
        }

        if (lid == 0) MBAR_ARRIVE(sb + 64 + 8 * s);

        if (tid == 0 && g + STAGES < NKS) {
            MBAR_WAIT(sb + 64 + 8 * s, ph);      // all 4 warps done with stage
            int ks = g + STAGES;
            const char* srcA = (const char*)g_A + (size_t)(mtb * NKS + ks) * A_STAGE;
            const char* srcB = (const char*)g_B + (size_t)(nt  * NKS + ks) * B_STAGE;
            MBAR_EXPECT_TX(sb + 8 * s, STAGE_BYTES);
            BULK_G2S(sA, srcA, A_STAGE, sb + 8 * s);
            BULK_G2S(sB, srcB, B_STAGE, sb + 8 * s);
        }

        if (++s == STAGES) { s = 0; ph ^= 1; }
    }

    // ---- epilogue: out = acc*scale - rowsum*zp*scale + bias ----
    const int t4 = lid >> 2;
    const int c2 = (lid & 3) * 2;
#pragma unroll
    for (int mt = 0; mt < 4; ++mt) {
        int m0 = mtb * 128 + mwarp * 64 + mt * 16 + t4;
        float rs0 = g_rowsum[m0];
        float rs1 = g_rowsum[m0 + 8];
        float* row0 = out + (size_t)m0 * DK;
        float* row1 = row0 + (size_t)8 * DK;
#pragma unroll
        for (int nj = 0; nj < 8; ++nj) {
            int n = nt * 128 + nwarp * 64 + nj * 8 + c2;
            float sc0 = __ldg(scale + n),     sc1 = __ldg(scale + n + 1);
            float bi0 = __ldg(bias + n),      bi1 = __ldg(bias + n + 1);
            float zs0 = (float)__ldg(zp + n)     * sc0;
            float zs1 = (float)__ldg(zp + n + 1) * sc1;
            float2 o0, o1;
            o0.x = acc[mt][nj][0] * sc0 + bi0 - rs0 * zs0;
            o0.y = acc[mt][nj][1] * sc1 + bi1 - rs0 * zs1;
            o1.x = acc[mt][nj][2] * sc0 + bi0 - rs1 * zs0;
            o1.y = acc[mt][nj][3] * sc1 + bi1 - rs1 * zs1;
            *reinterpret_cast<float2*>(row0 + n) = o0;
            *reinterpret_cast<float2*>(row1 + n) = o1;
        }
    }
}

// ---------------- launch ----------------
extern "C" void kernel_launch(void* const* d_in, const int* in_sizes, int n_in,
                              void* d_out, int out_size) {
    const float* x     = (const float*)d_in[0];
    const int*   q     = (const int*)  d_in[1];
    const float* scale = (const float*)d_in[2];
    const int*   zp    = (const int*)  d_in[3];
    const float* bias  = (const float*)d_in[4];
    float* out = (float*)d_out;

    cudaFuncSetAttribute(ffq_gemm_kernel,
                         cudaFuncAttributeMaxDynamicSharedMemorySize, SMEM_BYTES);

    pack_all_kernel<<<2 * NMT * NKS, 256>>>(x, q);   // 4096 blocks (A+B packs)
    rowsum_reduce_kernel<<<MTOT / 256, 256>>>();     // 16 blocks
    ffq_gemm_kernel<<<dim3(NNT, NMT), 128, SMEM_BYTES>>>(scale, zp, bias, out);
}

// round 10
// speedup vs baseline: 1.0603x; 1.0063x over previous
#include <cuda_runtime.h>
#include <cuda_fp16.h>
#include <cstdint>
#include <cstddef>

// ---------------- problem constants ----------------
static constexpr int DK   = 4096;          // inner dim == output dim
static constexpr int MTOT = 4096;          // B*S
static constexpr int TM = 128, TN = 128, TK = 64;
static constexpr int NMT = MTOT / TM;      // 32
static constexpr int NNT = DK / TN;        // 32
static constexpr int NKS = DK / TK;        // 64 k-stages, single pass
static constexpr int STAGES = 3;
static constexpr int A_STAGE = TM * TK * 2;              // 16384
static constexpr int B_STAGE = TK * TN * 2;              // 16384
static constexpr int STAGE_BYTES = A_STAGE + B_STAGE;    // 32768
static constexpr int SMEM_BYTES  = 1024 + STAGES * STAGE_BYTES; // 99328 -> 2 CTAs/SM

// ---------------- scratch (pre-packed, pre-swizzled fp16 tiles) -------------
__device__ __align__(1024) __half g_A[(size_t)NMT * NKS * TM * TK]; // 32MB
__device__ __align__(1024) __half g_B[(size_t)NNT * NKS * TK * TN]; // 32MB
__device__ float g_px[(size_t)NKS * MTOT]; // per-(ktile, row) partials, 1MB

// ---------------- helpers ----------------
__device__ __forceinline__ uint32_t smem_u32(const void* p) {
    uint32_t a;
    asm("{ .reg .u64 t; cvta.to.shared.u64 t, %1; cvt.u32.u64 %0, t; }"
        : "=r"(a) : "l"(p));
    return a;
}
// A tiles: 128B rows -> XOR bits[6:4] with bits[9:7]
__device__ __forceinline__ uint32_t swzA(uint32_t off) {
    return off ^ ((off >> 3) & 0x70);
}
// B tiles: 256B rows -> XOR bits[6:4] with bits[10:8]
__device__ __forceinline__ uint32_t swzB(uint32_t off) {
    return off ^ ((off >> 4) & 0x70);
}

#define MBAR_INIT(mbar, cnt) \
    asm volatile("mbarrier.init.shared.b64 [%0], %1;" :: "r"(mbar), "r"(cnt) : "memory")
#define MBAR_ARRIVE(mbar) \
    asm volatile("mbarrier.arrive.shared.b64 _, [%0];" :: "r"(mbar) : "memory")
#define MBAR_EXPECT_TX(mbar, bytes) \
    asm volatile("mbarrier.arrive.expect_tx.shared.b64 _, [%0], %1;" \
                 :: "r"(mbar), "r"(bytes) : "memory")
#define MBAR_WAIT(mbar, parity) do {                                          \
    asm volatile(                                                             \
        "{\n\t.reg .pred P1;\n\t"                                             \
        "W_%=:\n\t"                                                           \
        "mbarrier.try_wait.parity.acquire.cta.shared::cta.b64 P1, [%0], %1, 0x989680;\n\t" \
        "@P1 bra.uni D_%=;\n\t"                                               \
        "bra.uni W_%=;\n\t"                                                   \
        "D_%=:\n\t}"                                                          \
        :: "r"((uint32_t)(mbar)), "r"((uint32_t)(parity)) : "memory");        \
} while (0)
#define BULK_G2S(dst, src, bytes, mbar)                                       \
    asm volatile(                                                             \
        "cp.async.bulk.shared::cluster.global.mbarrier::complete_tx::bytes "  \
        "[%0], [%1], %2, [%3];"                                               \
        :: "r"((uint32_t)(dst)), "l"(src), "r"((uint32_t)(bytes)),            \
           "r"((uint32_t)(mbar)) : "memory")

#define LDSM_X4(r0, r1, r2, r3, addr)                                         \
    asm volatile("ldmatrix.sync.aligned.m8n8.x4.shared.b16 {%0,%1,%2,%3}, [%4];" \
        : "=r"(r0), "=r"(r1), "=r"(r2), "=r"(r3) : "r"(addr))
#define LDSM_X4_T(r0, r1, r2, r3, addr)                                       \
    asm volatile("ldmatrix.sync.aligned.m8n8.x4.trans.shared.b16 {%0,%1,%2,%3}, [%4];" \
        : "=r"(r0), "=r"(r1), "=r"(r2), "=r"(r3) : "r"(addr))

#define MMA16816F16(d, a, b0, b1)                                             \
    asm volatile(                                                             \
        "mma.sync.aligned.m16n8k16.row.col.f32.f16.f16.f32 "                  \
        "{%0,%1,%2,%3}, {%4,%5,%6,%7}, {%8,%9}, {%0,%1,%2,%3};"               \
        : "+f"((d)[0]), "+f"((d)[1]), "+f"((d)[2]), "+f"((d)[3])              \
        : "r"((a)[0]), "r"((a)[1]), "r"((a)[2]), "r"((a)[3]),                 \
          "r"(b0), "r"(b1))

// ---------------- merged pack kernel ----------------
// blocks [0, 2048):      A pack  (mt*64 + ks)  + per-(ks,row) partial sums
// blocks [2048, 4096):   B pack  (nt*64 + ks)
__global__ void __launch_bounds__(256) pack_all_kernel(const float* __restrict__ x,
                                                       const int* __restrict__ q) {
    int b = blockIdx.x;
    if (b < NMT * NKS) {
        int mt = b >> 6, ks = b & 63;
        size_t base = (size_t)b * A_STAGE;
#pragma unroll
        for (int p = 0; p < 4; p++) {
            int idx = threadIdx.x + p * 256;            // [0,1024)
            int ml = idx >> 3, k8 = idx & 7;
            size_t gm = (size_t)(mt * 128 + ml) * DK + ks * 64 + k8 * 8;
            float4 f0 = *reinterpret_cast<const float4*>(x + gm);
            float4 f1 = *reinterpret_cast<const float4*>(x + gm + 4);
            float v[8] = {f0.x, f0.y, f0.z, f0.w, f1.x, f1.y, f1.z, f1.w};
            uint32_t w[4];
            float s = 0.0f;
#pragma unroll
            for (int i = 0; i < 4; i++) {
                s += (v[2 * i] + v[2 * i + 1]);
                __half h0 = __float2half_rn(v[2 * i]);
                __half h1 = __float2half_rn(v[2 * i + 1]);
                w[i] = (uint32_t)__half_as_ushort(h0) |
                       ((uint32_t)__half_as_ushort(h1) << 16);
            }
            uint32_t off = swzA((uint32_t)(ml * 128 + k8 * 16));
            *reinterpret_cast<uint4*>((char*)g_A + base + off) =
                make_uint4(w[0], w[1], w[2], w[3]);
            // deterministic 8-lane tree sum (one row = aligned 8-lane group)
            s += __shfl_xor_sync(0xffffffffu, s, 1);
            s += __shfl_xor_sync(0xffffffffu, s, 2);
            s += __shfl_xor_sync(0xffffffffu, s, 4);
            if ((threadIdx.x & 7) == 0)
                g_px[(size_t)ks * MTOT + (mt * 128 + ml)] = s;   // [ks][row]
        }
    } else {
        b -= NMT * NKS;
        int nt = b >> 6, ks = b & 63;
        size_t base = (size_t)b * B_STAGE;
#pragma unroll
        for (int p = 0; p < 4; p++) {
            int idx = threadIdx.x + p * 256;            // [0,1024)
            int kl = idx >> 4, c8 = idx & 15;           // 64 rows x 16 chunks
            const int* src = q + (size_t)(ks * 64 + kl) * DK + nt * 128 + c8 * 8;
            int4 q0 = *reinterpret_cast<const int4*>(src);
            int4 q1 = *reinterpret_cast<const int4*>(src + 4);
            int vi[8] = {q0.x, q0.y, q0.z, q0.w, q1.x, q1.y, q1.z, q1.w};
            uint32_t w[4];
#pragma unroll
            for (int i = 0; i < 4; i++) {
                __half b0 = __float2half_rn((float)vi[2 * i]);
                __half b1 = __float2half_rn((float)vi[2 * i + 1]);
                w[i] = (uint32_t)__half_as_ushort(b0) |
                       ((uint32_t)__half_as_ushort(b1) << 16);
            }
            uint32_t off = swzB((uint32_t)(kl * 256 + c8 * 16));
            *reinterpret_cast<uint4*>((char*)g_B + base + off) =
                make_uint4(w[0], w[1], w[2], w[3]);
        }
    }
}

// ---------------- main GEMM: 4 warps, 64x64 warp tile, ping-pong frags ------
__global__ void __launch_bounds__(128, 2)
ffq_gemm_kernel(const float* __restrict__ scale, const int* __restrict__ zp,
                const float* __restrict__ bias, float* __restrict__ out) {
    extern __shared__ char smem_raw[];
    const uint32_t sbase = smem_u32(smem_raw);
    uint32_t sb = (sbase + 1023u) & ~1023u;                // ctrl base
    const uint32_t data = sb + 1024;                       // stage s at data + s*32768
    float* rs_s = reinterpret_cast<float*>(smem_raw + (sb - sbase) + 512); // 128 floats

    const int tid = threadIdx.x;
    const int wid = tid >> 5, lid = tid & 31;
    const int nt = blockIdx.x, mtb = blockIdx.y;
    const int mwarp = wid & 1;            // 2 M-halves of 64
    const int nwarp = wid >> 1;           // 2 N-halves of 64

    // full[s] @ sb+8s (tx-based), empty[s] @ sb+64+8s (4 warp arrivals)
    if (tid == 0) {
#pragma unroll
        for (int s = 0; s < STAGES; s++) {
            MBAR_INIT(sb + 8 * s, 1);
            MBAR_INIT(sb + 64 + 8 * s, 4);
        }
        asm volatile("fence.proxy.async.shared::cta;" ::: "memory");
    }
    __syncthreads();

    // prologue: fill stages 0..2 with ks = s
    if (tid == 0) {
#pragma unroll
        for (int s = 0; s < STAGES; s++) {
            const char* srcA = (const char*)g_A + (size_t)(mtb * NKS + s) * A_STAGE;
            const char* srcB = (const char*)g_B + (size_t)(nt  * NKS + s) * B_STAGE;
            uint32_t st = data + s * STAGE_BYTES;
            MBAR_EXPECT_TX(sb + 8 * s, STAGE_BYTES);
            BULK_G2S(st,           srcA, A_STAGE, sb + 8 * s);
            BULK_G2S(st + A_STAGE, srcB, B_STAGE, sb + 8 * s);
        }
    }

    // rowsums for this CTA's 128 rows (overlaps the stage-0 TMA fill);
    // fixed ks order -> deterministic, same order as before.
    {
        int row = mtb * 128 + tid;
        float rsum = 0.0f;
#pragma unroll 8
        for (int ks2 = 0; ks2 < NKS; ks2++)
            rsum += g_px[(size_t)ks2 * MTOT + row];
        rs_s[tid] = rsum;
    }
    __syncthreads();

    // per-lane ldmatrix address components
    const int lg = lid >> 3, li = lid & 7;
    const uint32_t xorc  = (uint32_t)li << 4;
    const uint32_t a_row = (uint32_t)(mwarp * 64 + (lg & 1) * 8 + li);   // + mt*16
    const uint32_t acolh = (uint32_t)((lg >> 1) * 16);                   // + k16*32
    const uint32_t b_klo = (uint32_t)((lg & 1) * 8 + li);                // + k16*16
    const uint32_t bcolh = (uint32_t)(nwarp * 128 + (lg >> 1) * 16);     // + ng*32

    float acc[4][8][4];
#pragma unroll
    for (int i = 0; i < 4; i++)
#pragma unroll
        for (int j = 0; j < 8; j++)
#pragma unroll
            for (int c = 0; c < 4; c++) acc[i][j][c] = 0.0f;

    int s = 0, ph = 0;
#pragma unroll 1
    for (int g = 0; g < NKS; ++g) {
        MBAR_WAIT(sb + 8 * s, ph);

        uint32_t sA = data + s * STAGE_BYTES;
        uint32_t sB = sA + A_STAGE;

        // ping-pong fragment buffers, parity-indexed (no register copies)
        uint32_t a_f[2][4][4], b_f[2][4][4];
        {   // prime k16 = 0 into buffer 0
            uint32_t ra = a_row * 128 + (acolh ^ xorc);
#pragma unroll
            for (int mt = 0; mt < 4; ++mt)
                LDSM_X4(a_f[0][mt][0], a_f[0][mt][1], a_f[0][mt][2], a_f[0][mt][3],
                        sA + ra + mt * (16 * 128));
            uint32_t rbbase = sB + b_klo * 256;
#pragma unroll
            for (int ng = 0; ng < 4; ++ng)
                LDSM_X4_T(b_f[0][ng][0], b_f[0][ng][1], b_f[0][ng][2], b_f[0][ng][3],
                          rbbase + (((uint32_t)(ng * 32) + bcolh) ^ xorc));
        }

#pragma unroll
        for (int k16 = 0; k16 < 4; ++k16) {
            const int cur = k16 & 1, nxt = cur ^ 1;
            if (k16 < 3) {   // prefetch next k16 group into the other buffer
                uint32_t ra = a_row * 128 +
                              (((uint32_t)((k16 + 1) * 32) + acolh) ^ xorc);
#pragma unroll
                for (int mt = 0; mt < 4; ++mt)
                    LDSM_X4(a_f[nxt][mt][0], a_f[nxt][mt][1],
                            a_f[nxt][mt][2], a_f[nxt][mt][3],
                            sA + ra + mt * (16 * 128));
                uint32_t rbbase = sB + (b_klo + (k16 + 1) * 16) * 256;
#pragma unroll
                for (int ng = 0; ng < 4; ++ng)
                    LDSM_X4_T(b_f[nxt][ng][0], b_f[nxt][ng][1],
                              b_f[nxt][ng][2], b_f[nxt][ng][3],
                              rbbase + (((uint32_t)(ng * 32) + bcolh) ^ xorc));
            }

            // 32 HMMAs on current fragments
#pragma unroll
            for (int mt = 0; mt < 4; ++mt)
#pragma unroll
                for (int ng = 0; ng < 4; ++ng) {
                    MMA16816F16(acc[mt][2 * ng],     a_f[cur][mt],
                                b_f[cur][ng][0], b_f[cur][ng][1]);
                    MMA16816F16(acc[mt][2 * ng + 1], a_f[cur][mt],
                                b_f[cur][ng][2], b_f[cur][ng][3]);
                }
        }

        if (lid == 0) MBAR_ARRIVE(sb + 64 + 8 * s);

        if (tid == 0 && g + STAGES < NKS) {
            MBAR_WAIT(sb + 64 + 8 * s, ph);      // all 4 warps done with stage
            int ks = g + STAGES;
            const char* srcA = (const char*)g_A + (size_t)(mtb * NKS + ks) * A_STAGE;
            const char* srcB = (const char*)g_B + (size_t)(nt  * NKS + ks) * B_STAGE;
            MBAR_EXPECT_TX(sb + 8 * s, STAGE_BYTES);
            BULK_G2S(sA, srcA, A_STAGE, sb + 8 * s);
            BULK_G2S(sB, srcB, B_STAGE, sb + 8 * s);
        }

        if (++s == STAGES) { s = 0; ph ^= 1; }
    }

    // ---- epilogue: out = acc*scale - rowsum*zp*scale + bias ----
    const int t4 = lid >> 2;
    const int c2 = (lid & 3) * 2;
#pragma unroll
    for (int mt = 0; mt < 4; ++mt) {
        int lr0 = mwarp * 64 + mt * 16 + t4;      // CTA-local row
        int m0 = mtb * 128 + lr0;
        float rs0 = rs_s[lr0];
        float rs1 = rs_s[lr0 + 8];
        float* row0 = out + (size_t)m0 * DK;
        float* row1 = row0 + (size_t)8 * DK;
#pragma unroll
        for (int nj = 0; nj < 8; ++nj) {
            int n = nt * 128 + nwarp * 64 + nj * 8 + c2;
            float sc0 = __ldg(scale + n),     sc1 = __ldg(scale + n + 1);
            float bi0 = __ldg(bias + n),      bi1 = __ldg(bias + n + 1);
            float zs0 = (float)__ldg(zp + n)     * sc0;
            float zs1 = (float)__ldg(zp + n + 1) * sc1;
            float2 o0, o1;
            o0.x = acc[mt][nj][0] * sc0 + bi0 - rs0 * zs0;
            o0.y = acc[mt][nj][1] * sc1 + bi1 - rs0 * zs1;
            o1.x = acc[mt][nj][2] * sc0 + bi0 - rs1 * zs0;
            o1.y = acc[mt][nj][3] * sc1 + bi1 - rs1 * zs1;
            *reinterpret_cast<float2*>(row0 + n) = o0;
            *reinterpret_cast<float2*>(row1 + n) = o1;
        }
    }
}

// ---------------- launch ----------------
extern "C" void kernel_launch(void* const* d_in, const int* in_sizes, int n_in,
                              void* d_out, int out_size) {
    const float* x     = (const float*)d_in[0];
    const int*   q     = (const int*)  d_in[1];
    const float* scale = (const float*)d_in[2];
    const int*   zp    = (const int*)  d_in[3];
    const float* bias  = (const float*)d_in[4];
    float* out = (float*)d_out;

    cudaFuncSetAttribute(ffq_gemm_kernel,
                         cudaFuncAttributeMaxDynamicSharedMemorySize, SMEM_BYTES);

    pack_all_kernel<<<2 * NMT * NKS, 256>>>(x, q);   // 4096 blocks (A+B packs)
    ffq_gemm_kernel<<<dim3(NNT, NMT), 128, SMEM_BYTES>>>(scale, zp, bias, out);
}